// round 1
// baseline (speedup 1.0000x reference)
#include <cuda_runtime.h>
#include <math.h>

// Problem constants
#define BB 4
#define SS 2048
#define DD 1024
#define HH 16
#define DK 64
#define MM (BB*SS)          // 8192
#define HD (HH*DK)          // 1024

// Scratch (allocation-free rule: __device__ globals)
__device__ float g_Q[MM*HD];
__device__ float g_K[MM*HD];
__device__ float g_V[MM*HD];
__device__ float g_A[MM*HD];

typedef unsigned long long u64;

__device__ __forceinline__ u64 fma2(u64 a, u64 b, u64 c) {
    u64 d;
    asm("fma.rn.f32x2 %0, %1, %2, %3;" : "=l"(d) : "l"(a), "l"(b), "l"(c));
    return d;
}
__device__ __forceinline__ u64 mul2(u64 a, u64 b) {
    u64 d;
    asm("mul.rn.f32x2 %0, %1, %2;" : "=l"(d) : "l"(a), "l"(b));
    return d;
}
__device__ __forceinline__ u64 dup2(float x) {
    u64 r;
    asm("mov.b64 %0, {%1, %1};" : "=l"(r) : "f"(x));
    return r;
}
__device__ __forceinline__ float2 unpk(u64 v) {
    float2 f;
    asm("mov.b64 {%0, %1}, %2;" : "=f"(f.x), "=f"(f.y) : "l"(v));
    return f;
}

// ---------------------------------------------------------------------------
// SGEMM: C[M,N] = A[M,K] * B[K,N], row-major fp32, M%128==0, N%128==0, K%8==0
// 128x128 block tile, BK=8, 256 threads, 8x8 per-thread tile.
// Inner product packed as f32x2 pairs along N (b-pairs natural from LDS.128).
// asel/csel select __device__ scratch buffers (avoids host symbol lookups).
// ---------------------------------------------------------------------------
__global__ __launch_bounds__(256) void sgemm128(
    const float* __restrict__ A, const float* __restrict__ B, float* __restrict__ C,
    int M, int N, int K, int asel, int csel)
{
    if (asel == 0) A = g_A;
    if      (csel == 0) C = g_Q;
    else if (csel == 1) C = g_K;
    else if (csel == 2) C = g_V;

    __shared__ float As[8][128];
    __shared__ float Bs[8][128];

    const int tid  = threadIdx.x;
    const int brow = blockIdx.y, bcol = blockIdx.x;
    const float* Ag = A + (size_t)brow * 128 * K;
    const float* Bg = B + bcol * 128;

    const int aRow = tid >> 1;          // 0..127
    const int aCol = (tid & 1) << 2;    // 0 or 4
    const int bRow = tid >> 5;          // 0..7
    const int bCol = (tid & 31) << 2;   // 0..124
    const int tr   = (tid >> 4) << 3;   // thread row base
    const int tc   = (tid & 15) << 3;   // thread col base

    u64 acc[8][4];
#pragma unroll
    for (int i = 0; i < 8; i++)
#pragma unroll
        for (int j = 0; j < 4; j++) acc[i][j] = 0ull;

    for (int k0 = 0; k0 < K; k0 += 8) {
        float4 av = *(const float4*)(Ag + (size_t)aRow * K + k0 + aCol);
        float4 bv = *(const float4*)(Bg + (size_t)(k0 + bRow) * N + bCol);
        As[aCol + 0][aRow] = av.x;
        As[aCol + 1][aRow] = av.y;
        As[aCol + 2][aRow] = av.z;
        As[aCol + 3][aRow] = av.w;
        *(float4*)(&Bs[bRow][bCol]) = bv;
        __syncthreads();

#pragma unroll
        for (int kk = 0; kk < 8; kk++) {
            float4 a0 = *(const float4*)(&As[kk][tr]);
            float4 a1 = *(const float4*)(&As[kk][tr + 4]);
            ulonglong2 bq0 = *(const ulonglong2*)(&Bs[kk][tc]);      // (b0,b1),(b2,b3)
            ulonglong2 bq1 = *(const ulonglong2*)(&Bs[kk][tc + 4]);  // (b4,b5),(b6,b7)
            float ar[8] = {a0.x, a0.y, a0.z, a0.w, a1.x, a1.y, a1.z, a1.w};
#pragma unroll
            for (int i = 0; i < 8; i++) {
                u64 ad = dup2(ar[i]);
                acc[i][0] = fma2(ad, bq0.x, acc[i][0]);
                acc[i][1] = fma2(ad, bq0.y, acc[i][1]);
                acc[i][2] = fma2(ad, bq1.x, acc[i][2]);
                acc[i][3] = fma2(ad, bq1.y, acc[i][3]);
            }
        }
        __syncthreads();
    }

    float* Cg = C + (size_t)(brow * 128 + tr) * N + bcol * 128 + tc;
#pragma unroll
    for (int i = 0; i < 8; i++) {
        float2 c0 = unpk(acc[i][0]), c1 = unpk(acc[i][1]);
        float2 c2 = unpk(acc[i][2]), c3 = unpk(acc[i][3]);
        float4 v0 = make_float4(c0.x, c0.y, c1.x, c1.y);
        float4 v1 = make_float4(c2.x, c2.y, c3.x, c3.y);
        *(float4*)(Cg + (size_t)i * N)     = v0;
        *(float4*)(Cg + (size_t)i * N + 4) = v1;
    }
}

// ---------------------------------------------------------------------------
// Causal flash attention, fp32, f32x2 inner products (paired along reduction).
// One block = one (b,h) and 64 query rows. 256 threads = 8 warps, each warp
// owns 8 query rows; each lane owns key/value columns {lane, lane+32}.
// Shared: Qs, Ks (key-major), Vt (dv-major transposed), Ps — all [64][68].
// ---------------------------------------------------------------------------
#define PAD 68
#define ATT_SMEM (4 * 64 * PAD * 4)

__global__ __launch_bounds__(256) void attn_kernel()
{
    extern __shared__ float sm[];
    float* Qs = sm;
    float* Ks = sm + 64 * PAD;
    float* Vt = sm + 2 * 64 * PAD;
    float* Ps = sm + 3 * 64 * PAD;

    const int tid  = threadIdx.x;
    const int w    = tid >> 5;
    const int lane = tid & 31;
    const int bh   = blockIdx.y;
    const int b    = bh >> 4;
    const int h    = bh & 15;
    const int q0   = blockIdx.x << 6;
    const size_t rowbase = ((size_t)b * SS) * HD + h * 64;

    // Load Q tile (pre-scaled by 1/sqrt(DK) = 0.125)
    for (int idx = tid; idx < 64 * 16; idx += 256) {
        int r = idx >> 4, c4 = (idx & 15) << 2;
        float4 v = *(const float4*)(g_Q + rowbase + (size_t)(q0 + r) * HD + c4);
        v.x *= 0.125f; v.y *= 0.125f; v.z *= 0.125f; v.w *= 0.125f;
        *(float4*)(Qs + r * PAD + c4) = v;
    }

    float m[8], l[8];
    u64 acc0[8], acc1[8];
#pragma unroll
    for (int i = 0; i < 8; i++) { m[i] = -1e30f; l[i] = 0.f; acc0[i] = 0ull; acc1[i] = 0ull; }

    const int ntiles = blockIdx.x + 1;   // causal: tiles j0 <= q0
    for (int t = 0; t < ntiles; t++) {
        const int j0 = t << 6;
        __syncthreads();   // protect Ks/Vt (and Qs on first pass) before rewrite
        for (int idx = tid; idx < 64 * 16; idx += 256) {
            int r = idx >> 4, c4 = (idx & 15) << 2;
            float4 kv = *(const float4*)(g_K + rowbase + (size_t)(j0 + r) * HD + c4);
            *(float4*)(Ks + r * PAD + c4) = kv;
            float4 vv = *(const float4*)(g_V + rowbase + (size_t)(j0 + r) * HD + c4);
            Vt[(c4 + 0) * PAD + r] = vv.x;
            Vt[(c4 + 1) * PAD + r] = vv.y;
            Vt[(c4 + 2) * PAD + r] = vv.z;
            Vt[(c4 + 3) * PAD + r] = vv.w;
        }
        __syncthreads();

        // Scores: s[qi][c] for c0=lane, c1=lane+32; paired over d parity
        u64 s0[8], s1[8];
#pragma unroll
        for (int i = 0; i < 8; i++) { s0[i] = 0ull; s1[i] = 0ull; }
        const float* Kr0 = Ks + lane * PAD;
        const float* Kr1 = Ks + (lane + 32) * PAD;
#pragma unroll
        for (int d4 = 0; d4 < 16; d4++) {
            ulonglong2 k0 = *(const ulonglong2*)(Kr0 + d4 * 4);
            ulonglong2 k1 = *(const ulonglong2*)(Kr1 + d4 * 4);
#pragma unroll
            for (int i = 0; i < 8; i++) {
                ulonglong2 q = *(const ulonglong2*)(Qs + (w * 8 + i) * PAD + d4 * 4);
                s0[i] = fma2(q.x, k0.x, s0[i]);
                s0[i] = fma2(q.y, k0.y, s0[i]);
                s1[i] = fma2(q.x, k1.x, s1[i]);
                s1[i] = fma2(q.y, k1.y, s1[i]);
            }
        }

        const bool diag = (j0 == q0);
#pragma unroll
        for (int i = 0; i < 8; i++) {
            const int qrow = w * 8 + i;
            float2 f0 = unpk(s0[i]); float sc0 = f0.x + f0.y;
            float2 f1 = unpk(s1[i]); float sc1 = f1.x + f1.y;
            if (diag) {
                if (lane      > qrow) sc0 = -1e30f;
                if (lane + 32 > qrow) sc1 = -1e30f;
            }
            float mx = fmaxf(sc0, sc1);
#pragma unroll
            for (int off = 16; off > 0; off >>= 1)
                mx = fmaxf(mx, __shfl_xor_sync(0xffffffffu, mx, off));
            float mn = fmaxf(m[i], mx);
            float p0 = __expf(sc0 - mn);
            float p1 = __expf(sc1 - mn);
            float corr = __expf(m[i] - mn);
            float rs = p0 + p1;
#pragma unroll
            for (int off = 16; off > 0; off >>= 1)
                rs += __shfl_xor_sync(0xffffffffu, rs, off);
            l[i] = l[i] * corr + rs;
            m[i] = mn;
            u64 c2 = dup2(corr);
            acc0[i] = mul2(acc0[i], c2);
            acc1[i] = mul2(acc1[i], c2);
            Ps[qrow * PAD + lane]      = p0;
            Ps[qrow * PAD + lane + 32] = p1;
        }
        __syncwarp();  // Ps is warp-private per row; make lane writes visible

        // PV: acc[qi][dv] += sum_k P[qi][k] * V[k][dv]; paired over k parity
        const float* Vr0 = Vt + lane * PAD;
        const float* Vr1 = Vt + (lane + 32) * PAD;
#pragma unroll
        for (int k4 = 0; k4 < 16; k4++) {
            ulonglong2 v0 = *(const ulonglong2*)(Vr0 + k4 * 4);
            ulonglong2 v1 = *(const ulonglong2*)(Vr1 + k4 * 4);
#pragma unroll
            for (int i = 0; i < 8; i++) {
                ulonglong2 p = *(const ulonglong2*)(Ps + (w * 8 + i) * PAD + k4 * 4);
                acc0[i] = fma2(p.x, v0.x, acc0[i]);
                acc0[i] = fma2(p.y, v0.y, acc0[i]);
                acc1[i] = fma2(p.x, v1.x, acc1[i]);
                acc1[i] = fma2(p.y, v1.y, acc1[i]);
            }
        }
    }

    // Epilogue: fold f32x2 halves, normalize, store
#pragma unroll
    for (int i = 0; i < 8; i++) {
        float inv = 1.0f / l[i];
        float2 a0 = unpk(acc0[i]);
        float2 a1 = unpk(acc1[i]);
        float o0 = (a0.x + a0.y) * inv;
        float o1 = (a1.x + a1.y) * inv;
        size_t orow = rowbase + (size_t)(q0 + w * 8 + i) * HD;
        g_A[orow + lane]      = o0;
        g_A[orow + lane + 32] = o1;
    }
}

// ---------------------------------------------------------------------------
// Inputs (metadata order): queries, keys, values, mask, W_Q, W_K, W_V, W_O
// mask is causal tril — handled analytically, input ignored.
// ---------------------------------------------------------------------------
extern "C" void kernel_launch(void* const* d_in, const int* in_sizes, int n_in,
                              void* d_out, int out_size)
{
    (void)in_sizes; (void)n_in; (void)out_size;
    const float* q  = (const float*)d_in[0];
    const float* k  = (const float*)d_in[1];
    const float* v  = (const float*)d_in[2];
    const float* wq = (const float*)d_in[4];
    const float* wk = (const float*)d_in[5];
    const float* wv = (const float*)d_in[6];
    const float* wo = (const float*)d_in[7];
    float* out = (float*)d_out;

    cudaFuncSetAttribute(attn_kernel,
                         cudaFuncAttributeMaxDynamicSharedMemorySize, ATT_SMEM);

    dim3 gg(HD / 128, MM / 128);   // (8, 64)
    dim3 blk(256);

    // Projections: csel selects g_Q/g_K/g_V as destination (asel=-1: use A arg)
    sgemm128<<<gg, blk>>>(q, wq, nullptr, MM, HD, DD, -1, 0);
    sgemm128<<<gg, blk>>>(k, wk, nullptr, MM, HD, DD, -1, 1);
    sgemm128<<<gg, blk>>>(v, wv, nullptr, MM, HD, DD, -1, 2);

    // Attention: g_Q,g_K,g_V -> g_A
    attn_kernel<<<dim3(SS / 64, BB * HH), blk, ATT_SMEM>>>();

    // Output projection: g_A @ W_O -> d_out (asel=0 selects g_A)
    sgemm128<<<gg, blk>>>(nullptr, wo, out, MM, DD, HD, 0, 3);
}

// round 3
// speedup vs baseline: 1.6405x; 1.6405x over previous
#include <cuda_runtime.h>
#include <cuda_bf16.h>
#include <math.h>
#include <cstdint>

// Problem constants
#define BB 4
#define SS 2048
#define DD 1024
#define HH 16
#define MM (BB*SS)          // 8192
#define HD 1024             // H*DK

typedef __nv_bfloat16 bf16;
typedef unsigned long long u64;

// ---------------- scratch (__device__ globals; no allocs allowed) ----------
__device__ float g_Q[MM*HD];
__device__ float g_K[MM*HD];
__device__ float g_V[MM*HD];
__device__ float g_A[MM*HD];
__device__ bf16 g_qh[MM*DD], g_ql[MM*DD];
__device__ bf16 g_kh[MM*DD], g_kl[MM*DD];
__device__ bf16 g_vh[MM*DD], g_vl[MM*DD];
__device__ bf16 g_ah[MM*DD], g_al[MM*DD];
__device__ bf16 g_wh[4][DD*HD], g_wl[4][DD*HD];   // transposed weights [N][K], hi/lo

// ---------------- PTX helpers ----------------------------------------------
__device__ __forceinline__ uint32_t smem_u32(const void* p) {
    uint32_t a;
    asm("{ .reg .u64 t; cvta.to.shared.u64 t, %1; cvt.u32.u64 %0, t; }"
        : "=r"(a) : "l"(p));
    return a;
}
__device__ __forceinline__ void cpa16(uint32_t s, const void* g) {
    asm volatile("cp.async.cg.shared.global [%0], [%1], 16;" :: "r"(s), "l"(g));
}
__device__ __forceinline__ void cpa_commit() {
    asm volatile("cp.async.commit_group;" ::: "memory");
}
__device__ __forceinline__ void ldsm4(uint32_t* r, uint32_t a) {
    asm volatile("ldmatrix.sync.aligned.m8n8.x4.shared.b16 {%0,%1,%2,%3}, [%4];"
                 : "=r"(r[0]), "=r"(r[1]), "=r"(r[2]), "=r"(r[3]) : "r"(a));
}
__device__ __forceinline__ void mma16816(float* c, const uint32_t* a,
                                         uint32_t b0, uint32_t b1) {
    asm volatile(
        "mma.sync.aligned.m16n8k16.row.col.f32.bf16.bf16.f32 "
        "{%0,%1,%2,%3}, {%4,%5,%6,%7}, {%8,%9}, {%0,%1,%2,%3};"
        : "+f"(c[0]), "+f"(c[1]), "+f"(c[2]), "+f"(c[3])
        : "r"(a[0]), "r"(a[1]), "r"(a[2]), "r"(a[3]), "r"(b0), "r"(b1));
}

// f32x2 helpers (attention)
__device__ __forceinline__ u64 fma2(u64 a, u64 b, u64 c) {
    u64 d; asm("fma.rn.f32x2 %0, %1, %2, %3;" : "=l"(d) : "l"(a), "l"(b), "l"(c)); return d;
}
__device__ __forceinline__ u64 mul2(u64 a, u64 b) {
    u64 d; asm("mul.rn.f32x2 %0, %1, %2;" : "=l"(d) : "l"(a), "l"(b)); return d;
}
__device__ __forceinline__ u64 dup2(float x) {
    u64 r; asm("mov.b64 %0, {%1, %1};" : "=l"(r) : "f"(x)); return r;
}
__device__ __forceinline__ float2 unpk(u64 v) {
    float2 f; asm("mov.b64 {%0, %1}, %2;" : "=f"(f.x), "=f"(f.y) : "l"(v)); return f;
}

// ---------------------------------------------------------------------------
// fp32 -> bf16 hi/lo split (elementwise, float4-vectorized). dsel picks dest.
// ---------------------------------------------------------------------------
__global__ __launch_bounds__(256) void cvt_hl(const float* __restrict__ src, int dsel)
{
    bf16 *h, *l;
    if      (dsel == 0) { h = g_qh; l = g_ql; }
    else if (dsel == 1) { h = g_kh; l = g_kl; }
    else if (dsel == 2) { h = g_vh; l = g_vl; }
    else                { h = g_ah; l = g_al; src = g_A; }
    int i = blockIdx.x * 256 + threadIdx.x;       // indexes float4
    float4 v = ((const float4*)src)[i];
    bf16 h0 = __float2bfloat16_rn(v.x); bf16 l0 = __float2bfloat16_rn(v.x - __bfloat162float(h0));
    bf16 h1 = __float2bfloat16_rn(v.y); bf16 l1 = __float2bfloat16_rn(v.y - __bfloat162float(h1));
    bf16 h2 = __float2bfloat16_rn(v.z); bf16 l2 = __float2bfloat16_rn(v.z - __bfloat162float(h2));
    bf16 h3 = __float2bfloat16_rn(v.w); bf16 l3 = __float2bfloat16_rn(v.w - __bfloat162float(h3));
    __nv_bfloat162 a, b;
    a.x = h0; a.y = h1; b.x = h2; b.y = h3;
    ((__nv_bfloat162*)h)[i*2] = a; ((__nv_bfloat162*)h)[i*2+1] = b;
    a.x = l0; a.y = l1; b.x = l2; b.y = l3;
    ((__nv_bfloat162*)l)[i*2] = a; ((__nv_bfloat162*)l)[i*2+1] = b;
}

// ---------------------------------------------------------------------------
// Weight transpose + hi/lo split: W[K=1024][N=1024] -> Wt_h/Wt_l [N][K] bf16
// ---------------------------------------------------------------------------
__global__ __launch_bounds__(256) void cvtT(const float* __restrict__ W, int dsel)
{
    bf16* Th = g_wh[dsel];
    bf16* Tl = g_wl[dsel];
    __shared__ float t[32][33];
    int bx = blockIdx.x * 32;   // n
    int by = blockIdx.y * 32;   // k
    int tx = threadIdx.x & 31, ty = threadIdx.x >> 5;   // ty 0..7
    for (int i = ty; i < 32; i += 8)
        t[i][tx] = W[(size_t)(by + i) * 1024 + bx + tx];
    __syncthreads();
    for (int i = ty; i < 32; i += 8) {
        float x = t[tx][i];                    // = W[by+tx][bx+i]
        bf16 hh = __float2bfloat16_rn(x);
        bf16 ll = __float2bfloat16_rn(x - __bfloat162float(hh));
        Th[(size_t)(bx + i) * 1024 + by + tx] = hh;
        Tl[(size_t)(bx + i) * 1024 + by + tx] = ll;
    }
}

// ---------------------------------------------------------------------------
// HMMA GEMM: C[8192,1024] = A[8192,1024] @ W^T (Wt stored [N][K])
// bf16 hi/lo fused 3-product (hi*hi + hi*lo + lo*hi) into fp32 accum.
// CTA 128x128, BK=32, 8 warps (4m x 2n -> warp tile 32x64), cp.async 2-stage.
// smem row pad: 32 -> 40 bf16 (80B) for conflict-free ldmatrix.
// ---------------------------------------------------------------------------
#define TEN_B 10240                 // bytes per tensor tile (128 rows * 80B)
#define STG_B (4*TEN_B)             // Ah,Al,Bh,Bl
#define G_SMEM (2*STG_B)            // 81920

__global__ __launch_bounds__(256) void mmagemm(float* __restrict__ Cout, int which)
{
    extern __shared__ char smem[];
    const bf16 *Ah, *Al, *Bhp, *Blp; float* C;
    if      (which == 0) { Ah=g_qh; Al=g_ql; Bhp=g_wh[0]; Blp=g_wl[0]; C=g_Q;  }
    else if (which == 1) { Ah=g_kh; Al=g_kl; Bhp=g_wh[1]; Blp=g_wl[1]; C=g_K;  }
    else if (which == 2) { Ah=g_vh; Al=g_vl; Bhp=g_wh[2]; Blp=g_wl[2]; C=g_V;  }
    else                 { Ah=g_ah; Al=g_al; Bhp=g_wh[3]; Blp=g_wl[3]; C=Cout; }

    const uint32_t sb = smem_u32(smem);
    const int tid = threadIdx.x, wid = tid >> 5, lane = tid & 31;
    const int wm = wid & 3, wn = wid >> 2;
    const int m0 = blockIdx.y * 128, n0 = blockIdx.x * 128;

    float acc[2][8][4];
#pragma unroll
    for (int i = 0; i < 2; i++)
#pragma unroll
        for (int j = 0; j < 8; j++)
#pragma unroll
            for (int q = 0; q < 4; q++) acc[i][j][q] = 0.f;

    // per-thread load coords (2 rows per tensor)
    const int r0 = tid >> 2, ch0 = tid & 3;            // + 0
    const int r1 = (tid + 256) >> 2, ch1 = tid & 3;    // + 64 rows

    auto load_stage = [&](int it, int s) {
        const int kk = it << 5;
        const uint32_t st = sb + s * STG_B;
        const size_t ga0 = (size_t)(m0 + r0) * 1024 + kk + ch0 * 8;
        const size_t ga1 = (size_t)(m0 + r1) * 1024 + kk + ch1 * 8;
        const size_t gb0 = (size_t)(n0 + r0) * 1024 + kk + ch0 * 8;
        const size_t gb1 = (size_t)(n0 + r1) * 1024 + kk + ch1 * 8;
        const uint32_t so0 = r0 * 80 + ch0 * 16;
        const uint32_t so1 = r1 * 80 + ch1 * 16;
        cpa16(st            + so0, Ah  + ga0);
        cpa16(st            + so1, Ah  + ga1);
        cpa16(st +   TEN_B  + so0, Al  + ga0);
        cpa16(st +   TEN_B  + so1, Al  + ga1);
        cpa16(st + 2*TEN_B  + so0, Bhp + gb0);
        cpa16(st + 2*TEN_B  + so1, Bhp + gb1);
        cpa16(st + 3*TEN_B  + so0, Blp + gb0);
        cpa16(st + 3*TEN_B  + so1, Blp + gb1);
        cpa_commit();
    };

    // ldmatrix lane offsets
    const uint32_t aoff = (uint32_t)(wm * 32 + (lane & 15)) * 80 + ((lane >> 4) << 3) * 2;
    const uint32_t boff = (uint32_t)(wn * 64 + ((lane >> 4) << 3) + (lane & 7)) * 80
                        + (((lane >> 3) & 1) << 3) * 2;

    load_stage(0, 0);
    const int NIT = 32;
    for (int it = 0; it < NIT; it++) {
        const int s = it & 1;
        if (it + 1 < NIT) {
            load_stage(it + 1, s ^ 1);
            asm volatile("cp.async.wait_group 1;" ::: "memory");
        } else {
            asm volatile("cp.async.wait_group 0;" ::: "memory");
        }
        __syncthreads();

        const uint32_t st = sb + s * STG_B;
#pragma unroll
        for (int k16 = 0; k16 < 2; k16++) {
            const uint32_t kb = (uint32_t)(k16 * 16 * 2);
            uint32_t aH[2][4], aL[2][4];
            ldsm4(aH[0], st            + aoff + kb);
            ldsm4(aH[1], st            + aoff + kb + 16 * 80);
            ldsm4(aL[0], st +   TEN_B  + aoff + kb);
            ldsm4(aL[1], st +   TEN_B  + aoff + kb + 16 * 80);
            uint32_t bH[4][4], bL[4][4];
#pragma unroll
            for (int p = 0; p < 4; p++) {
                ldsm4(bH[p], st + 2*TEN_B + boff + kb + (uint32_t)p * 16 * 80);
                ldsm4(bL[p], st + 3*TEN_B + boff + kb + (uint32_t)p * 16 * 80);
            }
#pragma unroll
            for (int mi = 0; mi < 2; mi++)
#pragma unroll
                for (int nj = 0; nj < 8; nj++) {
                    const uint32_t* bh = &bH[nj >> 1][(nj & 1) * 2];
                    const uint32_t* bl = &bL[nj >> 1][(nj & 1) * 2];
                    mma16816(acc[mi][nj], aH[mi], bh[0], bh[1]);
                    mma16816(acc[mi][nj], aH[mi], bl[0], bl[1]);
                    mma16816(acc[mi][nj], aL[mi], bh[0], bh[1]);
                }
        }
        __syncthreads();
    }

    // epilogue
#pragma unroll
    for (int mi = 0; mi < 2; mi++)
#pragma unroll
        for (int nj = 0; nj < 8; nj++) {
            const int row = m0 + wm * 32 + mi * 16 + (lane >> 2);
            const int col = n0 + wn * 64 + nj * 8 + (lane & 3) * 2;
            *(float2*)(C + (size_t)row * 1024 + col)
                = make_float2(acc[mi][nj][0], acc[mi][nj][1]);
            *(float2*)(C + (size_t)(row + 8) * 1024 + col)
                = make_float2(acc[mi][nj][2], acc[mi][nj][3]);
        }
}

// ---------------------------------------------------------------------------
// Causal flash attention, fp32 SIMT, f32x2 inner products. 2 CTAs/SM target.
// ---------------------------------------------------------------------------
#define PAD 68
#define ATT_SMEM (4 * 64 * PAD * 4)

__global__ __launch_bounds__(256, 2) void attn_kernel()
{
    extern __shared__ float sm[];
    float* Qs = sm;
    float* Ks = sm + 64 * PAD;
    float* Vt = sm + 2 * 64 * PAD;
    float* Ps = sm + 3 * 64 * PAD;

    const int tid  = threadIdx.x;
    const int w    = tid >> 5;
    const int lane = tid & 31;
    const int bh   = blockIdx.y;
    const int b    = bh >> 4;
    const int h    = bh & 15;
    const int qt   = (int)gridDim.x - 1 - blockIdx.x;   // long tiles first
    const int q0   = qt << 6;
    const size_t rowbase = ((size_t)b * SS) * HD + h * 64;

    for (int idx = tid; idx < 64 * 16; idx += 256) {
        int r = idx >> 4, c4 = (idx & 15) << 2;
        float4 v = *(const float4*)(g_Q + rowbase + (size_t)(q0 + r) * HD + c4);
        v.x *= 0.125f; v.y *= 0.125f; v.z *= 0.125f; v.w *= 0.125f;
        *(float4*)(Qs + r * PAD + c4) = v;
    }

    float m[8], l[8];
    u64 acc0[8], acc1[8];
#pragma unroll
    for (int i = 0; i < 8; i++) { m[i] = -1e30f; l[i] = 0.f; acc0[i] = 0ull; acc1[i] = 0ull; }

    const int ntiles = qt + 1;
    for (int t = 0; t < ntiles; t++) {
        const int j0 = t << 6;
        __syncthreads();
        for (int idx = tid; idx < 64 * 16; idx += 256) {
            int r = idx >> 4, c4 = (idx & 15) << 2;
            float4 kv = *(const float4*)(g_K + rowbase + (size_t)(j0 + r) * HD + c4);
            *(float4*)(Ks + r * PAD + c4) = kv;
            float4 vv = *(const float4*)(g_V + rowbase + (size_t)(j0 + r) * HD + c4);
            Vt[(c4 + 0) * PAD + r] = vv.x;
            Vt[(c4 + 1) * PAD + r] = vv.y;
            Vt[(c4 + 2) * PAD + r] = vv.z;
            Vt[(c4 + 3) * PAD + r] = vv.w;
        }
        __syncthreads();

        u64 s0[8], s1[8];
#pragma unroll
        for (int i = 0; i < 8; i++) { s0[i] = 0ull; s1[i] = 0ull; }
        const float* Kr0 = Ks + lane * PAD;
        const float* Kr1 = Ks + (lane + 32) * PAD;
#pragma unroll
        for (int d4 = 0; d4 < 16; d4++) {
            ulonglong2 k0 = *(const ulonglong2*)(Kr0 + d4 * 4);
            ulonglong2 k1 = *(const ulonglong2*)(Kr1 + d4 * 4);
#pragma unroll
            for (int i = 0; i < 8; i++) {
                ulonglong2 q = *(const ulonglong2*)(Qs + (w * 8 + i) * PAD + d4 * 4);
                s0[i] = fma2(q.x, k0.x, s0[i]);
                s0[i] = fma2(q.y, k0.y, s0[i]);
                s1[i] = fma2(q.x, k1.x, s1[i]);
                s1[i] = fma2(q.y, k1.y, s1[i]);
            }
        }

        const bool diag = (j0 == q0);
#pragma unroll
        for (int i = 0; i < 8; i++) {
            const int qrow = w * 8 + i;
            float2 f0 = unpk(s0[i]); float sc0 = f0.x + f0.y;
            float2 f1 = unpk(s1[i]); float sc1 = f1.x + f1.y;
            if (diag) {
                if (lane      > qrow) sc0 = -1e30f;
                if (lane + 32 > qrow) sc1 = -1e30f;
            }
            float mx = fmaxf(sc0, sc1);
#pragma unroll
            for (int off = 16; off > 0; off >>= 1)
                mx = fmaxf(mx, __shfl_xor_sync(0xffffffffu, mx, off));
            float mn = fmaxf(m[i], mx);
            float p0 = __expf(sc0 - mn);
            float p1 = __expf(sc1 - mn);
            float corr = __expf(m[i] - mn);
            float rs = p0 + p1;
#pragma unroll
            for (int off = 16; off > 0; off >>= 1)
                rs += __shfl_xor_sync(0xffffffffu, rs, off);
            l[i] = l[i] * corr + rs;
            m[i] = mn;
            u64 c2 = dup2(corr);
            acc0[i] = mul2(acc0[i], c2);
            acc1[i] = mul2(acc1[i], c2);
            Ps[qrow * PAD + lane]      = p0;
            Ps[qrow * PAD + lane + 32] = p1;
        }
        __syncwarp();

        const float* Vr0 = Vt + lane * PAD;
        const float* Vr1 = Vt + (lane + 32) * PAD;
#pragma unroll
        for (int k4 = 0; k4 < 16; k4++) {
            ulonglong2 v0 = *(const ulonglong2*)(Vr0 + k4 * 4);
            ulonglong2 v1 = *(const ulonglong2*)(Vr1 + k4 * 4);
#pragma unroll
            for (int i = 0; i < 8; i++) {
                ulonglong2 p = *(const ulonglong2*)(Ps + (w * 8 + i) * PAD + k4 * 4);
                acc0[i] = fma2(p.x, v0.x, acc0[i]);
                acc0[i] = fma2(p.y, v0.y, acc0[i]);
                acc1[i] = fma2(p.x, v1.x, acc1[i]);
                acc1[i] = fma2(p.y, v1.y, acc1[i]);
            }
        }
    }

#pragma unroll
    for (int i = 0; i < 8; i++) {
        float inv = 1.0f / l[i];
        float2 a0 = unpk(acc0[i]);
        float2 a1 = unpk(acc1[i]);
        float o0 = (a0.x + a0.y) * inv;
        float o1 = (a1.x + a1.y) * inv;
        size_t orow = rowbase + (size_t)(q0 + w * 8 + i) * HD;
        g_A[orow + lane]      = o0;
        g_A[orow + lane + 32] = o1;
    }
}

// ---------------------------------------------------------------------------
// Inputs: queries, keys, values, mask(ignored), W_Q, W_K, W_V, W_O
// ---------------------------------------------------------------------------
extern "C" void kernel_launch(void* const* d_in, const int* in_sizes, int n_in,
                              void* d_out, int out_size)
{
    (void)in_sizes; (void)n_in; (void)out_size;
    const float* q  = (const float*)d_in[0];
    const float* k  = (const float*)d_in[1];
    const float* v  = (const float*)d_in[2];
    const float* wq = (const float*)d_in[4];
    const float* wk = (const float*)d_in[5];
    const float* wv = (const float*)d_in[6];
    const float* wo = (const float*)d_in[7];
    float* out = (float*)d_out;

    cudaFuncSetAttribute(mmagemm,
                         cudaFuncAttributeMaxDynamicSharedMemorySize, G_SMEM);
    cudaFuncSetAttribute(attn_kernel,
                         cudaFuncAttributeMaxDynamicSharedMemorySize, ATT_SMEM);

    const int nCvt = (MM * DD / 4) / 256;     // 8192 blocks

    // bf16 hi/lo conversions
    cvt_hl<<<nCvt, 256>>>(q, 0);
    cvt_hl<<<nCvt, 256>>>(k, 1);
    cvt_hl<<<nCvt, 256>>>(v, 2);
    cvtT<<<dim3(32, 32), 256>>>(wq, 0);
    cvtT<<<dim3(32, 32), 256>>>(wk, 1);
    cvtT<<<dim3(32, 32), 256>>>(wv, 2);
    cvtT<<<dim3(32, 32), 256>>>(wo, 3);

    // HMMA projections -> fp32 g_Q/g_K/g_V
    dim3 gg(HD / 128, MM / 128);              // (8, 64)
    mmagemm<<<gg, 256, G_SMEM>>>(nullptr, 0);
    mmagemm<<<gg, 256, G_SMEM>>>(nullptr, 1);
    mmagemm<<<gg, 256, G_SMEM>>>(nullptr, 2);

    // attention -> g_A
    attn_kernel<<<dim3(SS / 64, BB * HH), 256, ATT_SMEM>>>();

    // output projection
    cvt_hl<<<nCvt, 256>>>(nullptr, 3);
    mmagemm<<<gg, 256, G_SMEM>>>(out, 3);
}

// round 4
// speedup vs baseline: 2.8086x; 1.7121x over previous
#include <cuda_runtime.h>
#include <cuda_bf16.h>
#include <math.h>
#include <cstdint>

// Problem constants
#define BB 4
#define SS 2048
#define DD 1024
#define HH 16
#define MM (BB*SS)          // 8192
#define HD 1024             // H*DK

typedef __nv_bfloat16 bf16;

// ---------------- scratch (__device__ globals; no allocs allowed) ----------
__device__ bf16 g_qh[MM*DD], g_ql[MM*DD];          // input splits
__device__ bf16 g_kh[MM*DD], g_kl[MM*DD];
__device__ bf16 g_vh[MM*DD], g_vl[MM*DD];
__device__ bf16 g_wh[4][DD*HD], g_wl[4][DD*HD];    // weights^T [N][K] hi/lo
__device__ bf16 g_pqh[MM*HD], g_pql[MM*HD];        // projected Q (pre-scaled)
__device__ bf16 g_pkh[MM*HD], g_pkl[MM*HD];        // projected K
__device__ bf16 g_pvh[MM*HD], g_pvl[MM*HD];        // projected V
__device__ bf16 g_poh[MM*HD], g_pol[MM*HD];        // attention output

// ---------------- PTX helpers ----------------------------------------------
__device__ __forceinline__ uint32_t smem_u32(const void* p) {
    uint32_t a;
    asm("{ .reg .u64 t; cvta.to.shared.u64 t, %1; cvt.u32.u64 %0, t; }"
        : "=r"(a) : "l"(p));
    return a;
}
__device__ __forceinline__ void cpa16(uint32_t s, const void* g) {
    asm volatile("cp.async.cg.shared.global [%0], [%1], 16;" :: "r"(s), "l"(g));
}
__device__ __forceinline__ void cpa_commit() {
    asm volatile("cp.async.commit_group;" ::: "memory");
}
__device__ __forceinline__ void ldsm4(uint32_t* r, uint32_t a) {
    asm volatile("ldmatrix.sync.aligned.m8n8.x4.shared.b16 {%0,%1,%2,%3}, [%4];"
                 : "=r"(r[0]), "=r"(r[1]), "=r"(r[2]), "=r"(r[3]) : "r"(a));
}
__device__ __forceinline__ void ldsm4t(uint32_t* r, uint32_t a) {
    asm volatile("ldmatrix.sync.aligned.m8n8.x4.trans.shared.b16 {%0,%1,%2,%3}, [%4];"
                 : "=r"(r[0]), "=r"(r[1]), "=r"(r[2]), "=r"(r[3]) : "r"(a));
}
__device__ __forceinline__ void mma16816(float* c, const uint32_t* a,
                                         uint32_t b0, uint32_t b1) {
    asm volatile(
        "mma.sync.aligned.m16n8k16.row.col.f32.bf16.bf16.f32 "
        "{%0,%1,%2,%3}, {%4,%5,%6,%7}, {%8,%9}, {%0,%1,%2,%3};"
        : "+f"(c[0]), "+f"(c[1]), "+f"(c[2]), "+f"(c[3])
        : "r"(a[0]), "r"(a[1]), "r"(a[2]), "r"(a[3]), "r"(b0), "r"(b1));
}
// pack2(v0,v1): low half = bf16(v0), high half = bf16(v1)
__device__ __forceinline__ uint32_t pk2(float v0, float v1) {
    uint32_t d;
    asm("cvt.rn.bf16x2.f32 %0, %1, %2;" : "=r"(d) : "f"(v1), "f"(v0));
    return d;
}
// hi/lo split of a float pair; writes packed bf16x2 hi and lo words
__device__ __forceinline__ void split2(float v0, float v1, uint32_t& hi, uint32_t& lo) {
    hi = pk2(v0, v1);
    float h0 = __uint_as_float(hi << 16);
    float h1 = __uint_as_float(hi & 0xffff0000u);
    lo = pk2(v0 - h0, v1 - h1);
}

// ---------------------------------------------------------------------------
// fp32 -> bf16 hi/lo split of inputs (elementwise, float4-vectorized).
// ---------------------------------------------------------------------------
__global__ __launch_bounds__(256) void cvt_hl(const float* __restrict__ src, int dsel)
{
    bf16 *h, *l;
    if      (dsel == 0) { h = g_qh; l = g_ql; }
    else if (dsel == 1) { h = g_kh; l = g_kl; }
    else                { h = g_vh; l = g_vl; }
    int i = blockIdx.x * 256 + threadIdx.x;       // indexes float4
    float4 v = ((const float4*)src)[i];
    uint32_t h01, l01, h23, l23;
    split2(v.x, v.y, h01, l01);
    split2(v.z, v.w, h23, l23);
    ((uint32_t*)h)[i*2]   = h01; ((uint32_t*)h)[i*2+1] = h23;
    ((uint32_t*)l)[i*2]   = l01; ((uint32_t*)l)[i*2+1] = l23;
}

// ---------------------------------------------------------------------------
// Weight transpose + hi/lo split: W[K=1024][N=1024] -> Wt_h/Wt_l [N][K] bf16
// ---------------------------------------------------------------------------
__global__ __launch_bounds__(256) void cvtT(const float* __restrict__ W, int dsel)
{
    bf16* Th = g_wh[dsel];
    bf16* Tl = g_wl[dsel];
    __shared__ float t[32][33];
    int bx = blockIdx.x * 32;   // n
    int by = blockIdx.y * 32;   // k
    int tx = threadIdx.x & 31, ty = threadIdx.x >> 5;
    for (int i = ty; i < 32; i += 8)
        t[i][tx] = W[(size_t)(by + i) * 1024 + bx + tx];
    __syncthreads();
    for (int i = ty; i < 32; i += 8) {
        float x = t[tx][i];                    // = W[by+tx][bx+i]
        bf16 hh = __float2bfloat16_rn(x);
        bf16 ll = __float2bfloat16_rn(x - __bfloat162float(hh));
        Th[(size_t)(bx + i) * 1024 + by + tx] = hh;
        Tl[(size_t)(bx + i) * 1024 + by + tx] = ll;
    }
}

// ---------------------------------------------------------------------------
// HMMA GEMM: C[8192,1024] = A[8192,1024] @ W^T (Wt stored [N][K])
// hi/lo fused 3-product into fp32 accum. CTA 128x128, BK=32, 8 warps,
// cp.async 2-stage, 80B-padded rows.
// which 0..2: write bf16 hi/lo projected outputs (Q scaled by 0.125)
// which 3:    write fp32 to Cout.
// ---------------------------------------------------------------------------
#define TEN_B 10240                 // 128 rows * 80B
#define STG_B (4*TEN_B)
#define G_SMEM (2*STG_B)            // 81920

__global__ __launch_bounds__(256) void mmagemm(float* __restrict__ Cout, int which)
{
    extern __shared__ char smem[];
    const bf16 *Ah, *Al, *Bhp, *Blp;
    bf16 *Chi = nullptr, *Clo = nullptr;
    float scale = 1.f;
    if      (which == 0) { Ah=g_qh;  Al=g_ql;  Bhp=g_wh[0]; Blp=g_wl[0]; Chi=g_pqh; Clo=g_pql; scale=0.125f; }
    else if (which == 1) { Ah=g_kh;  Al=g_kl;  Bhp=g_wh[1]; Blp=g_wl[1]; Chi=g_pkh; Clo=g_pkl; }
    else if (which == 2) { Ah=g_vh;  Al=g_vl;  Bhp=g_wh[2]; Blp=g_wl[2]; Chi=g_pvh; Clo=g_pvl; }
    else                 { Ah=g_poh; Al=g_pol; Bhp=g_wh[3]; Blp=g_wl[3]; }

    const uint32_t sb = smem_u32(smem);
    const int tid = threadIdx.x, wid = tid >> 5, lane = tid & 31;
    const int wm = wid & 3, wn = wid >> 2;
    const int m0 = blockIdx.y * 128, n0 = blockIdx.x * 128;

    float acc[2][8][4];
#pragma unroll
    for (int i = 0; i < 2; i++)
#pragma unroll
        for (int j = 0; j < 8; j++)
#pragma unroll
            for (int q = 0; q < 4; q++) acc[i][j][q] = 0.f;

    const int r0 = tid >> 2, ch0 = tid & 3;
    const int r1 = (tid + 256) >> 2, ch1 = tid & 3;

    auto load_stage = [&](int it, int s) {
        const int kk = it << 5;
        const uint32_t st = sb + s * STG_B;
        const size_t ga0 = (size_t)(m0 + r0) * 1024 + kk + ch0 * 8;
        const size_t ga1 = (size_t)(m0 + r1) * 1024 + kk + ch1 * 8;
        const size_t gb0 = (size_t)(n0 + r0) * 1024 + kk + ch0 * 8;
        const size_t gb1 = (size_t)(n0 + r1) * 1024 + kk + ch1 * 8;
        const uint32_t so0 = r0 * 80 + ch0 * 16;
        const uint32_t so1 = r1 * 80 + ch1 * 16;
        cpa16(st            + so0, Ah  + ga0);
        cpa16(st            + so1, Ah  + ga1);
        cpa16(st +   TEN_B  + so0, Al  + ga0);
        cpa16(st +   TEN_B  + so1, Al  + ga1);
        cpa16(st + 2*TEN_B  + so0, Bhp + gb0);
        cpa16(st + 2*TEN_B  + so1, Bhp + gb1);
        cpa16(st + 3*TEN_B  + so0, Blp + gb0);
        cpa16(st + 3*TEN_B  + so1, Blp + gb1);
        cpa_commit();
    };

    const uint32_t aoff = (uint32_t)(wm * 32 + (lane & 15)) * 80 + ((lane >> 4) << 3) * 2;
    const uint32_t boff = (uint32_t)(wn * 64 + ((lane >> 4) << 3) + (lane & 7)) * 80
                        + (((lane >> 3) & 1) << 3) * 2;

    load_stage(0, 0);
    const int NIT = 32;
    for (int it = 0; it < NIT; it++) {
        const int s = it & 1;
        if (it + 1 < NIT) {
            load_stage(it + 1, s ^ 1);
            asm volatile("cp.async.wait_group 1;" ::: "memory");
        } else {
            asm volatile("cp.async.wait_group 0;" ::: "memory");
        }
        __syncthreads();

        const uint32_t st = sb + s * STG_B;
#pragma unroll
        for (int k16 = 0; k16 < 2; k16++) {
            const uint32_t kb = (uint32_t)(k16 * 16 * 2);
            uint32_t aH[2][4], aL[2][4];
            ldsm4(aH[0], st            + aoff + kb);
            ldsm4(aH[1], st            + aoff + kb + 16 * 80);
            ldsm4(aL[0], st +   TEN_B  + aoff + kb);
            ldsm4(aL[1], st +   TEN_B  + aoff + kb + 16 * 80);
            uint32_t bH[4][4], bL[4][4];
#pragma unroll
            for (int p = 0; p < 4; p++) {
                ldsm4(bH[p], st + 2*TEN_B + boff + kb + (uint32_t)p * 16 * 80);
                ldsm4(bL[p], st + 3*TEN_B + boff + kb + (uint32_t)p * 16 * 80);
            }
#pragma unroll
            for (int mi = 0; mi < 2; mi++)
#pragma unroll
                for (int nj = 0; nj < 8; nj++) {
                    const uint32_t* bh = &bH[nj >> 1][(nj & 1) * 2];
                    const uint32_t* bl = &bL[nj >> 1][(nj & 1) * 2];
                    mma16816(acc[mi][nj], aH[mi], bh[0], bh[1]);
                    mma16816(acc[mi][nj], aH[mi], bl[0], bl[1]);
                    mma16816(acc[mi][nj], aL[mi], bh[0], bh[1]);
                }
        }
        __syncthreads();
    }

    // epilogue
#pragma unroll
    for (int mi = 0; mi < 2; mi++)
#pragma unroll
        for (int nj = 0; nj < 8; nj++) {
            const int row = m0 + wm * 32 + mi * 16 + (lane >> 2);
            const int col = n0 + wn * 64 + nj * 8 + (lane & 3) * 2;
            if (which == 3) {
                *(float2*)(Cout + (size_t)row * 1024 + col)
                    = make_float2(acc[mi][nj][0], acc[mi][nj][1]);
                *(float2*)(Cout + (size_t)(row + 8) * 1024 + col)
                    = make_float2(acc[mi][nj][2], acc[mi][nj][3]);
            } else {
                uint32_t hh, ll;
                split2(acc[mi][nj][0]*scale, acc[mi][nj][1]*scale, hh, ll);
                *(uint32_t*)(Chi + (size_t)row * 1024 + col) = hh;
                *(uint32_t*)(Clo + (size_t)row * 1024 + col) = ll;
                split2(acc[mi][nj][2]*scale, acc[mi][nj][3]*scale, hh, ll);
                *(uint32_t*)(Chi + (size_t)(row + 8) * 1024 + col) = hh;
                *(uint32_t*)(Clo + (size_t)(row + 8) * 1024 + col) = ll;
            }
        }
}

// ---------------------------------------------------------------------------
// HMMA causal flash attention. 128 threads (4 warps), q-tile 64, key-tile 64.
// Warp w owns q rows w*16..+15. QK: Qh*Kh + Qh*Kl + Ql*Kh. PV: Ph*Vh + Ph*Vl
// + Pl*Vh with P split from fp32 registers. K/V cp.async double-buffered.
// smem rows padded to 72 bf16 (144B) — conflict-free ldmatrix/cp.async.
// ---------------------------------------------------------------------------
#define T_BYTES (64*144)            // 9216 per tensor tile
#define ST_SZ   (4*T_BYTES)         // Kh,Kl,Vh,Vl
#define ATT_SMEM (2*T_BYTES + 2*ST_SZ)   // 92160

__global__ __launch_bounds__(128) void attn_mma()
{
    extern __shared__ char sm8[];
    const uint32_t sb = smem_u32(sm8);
    const int tid = threadIdx.x, w = tid >> 5, lane = tid & 31;
    const int bh = blockIdx.y, b = bh >> 4, h = bh & 15;
    const int qt = (int)gridDim.x - 1 - blockIdx.x;     // long tiles first
    const int q0 = qt << 6;
    const size_t rowbase = (size_t)b * SS * HD + h * 64;

    // ---- load Q tile (hi+lo), group 0 ----
#pragma unroll
    for (int i = 0; i < 4; i++) {
        int op = tid + (i << 7);
        int r = op >> 3, ch = op & 7;
        size_t g = rowbase + (size_t)(q0 + r) * HD + ch * 8;
        uint32_t so = (uint32_t)r * 144 + ch * 16;
        cpa16(sb + so,           g_pqh + g);
        cpa16(sb + T_BYTES + so, g_pql + g);
    }
    cpa_commit();

    auto load_kv = [&](int t, int s) {
        const int j0 = t << 6;
        const uint32_t st = sb + 2 * T_BYTES + s * ST_SZ;
#pragma unroll
        for (int i = 0; i < 4; i++) {
            int op = tid + (i << 7);
            int r = op >> 3, ch = op & 7;
            size_t g = rowbase + (size_t)(j0 + r) * HD + ch * 8;
            uint32_t so = (uint32_t)r * 144 + ch * 16;
            cpa16(st              + so, g_pkh + g);
            cpa16(st +   T_BYTES  + so, g_pkl + g);
            cpa16(st + 2*T_BYTES  + so, g_pvh + g);
            cpa16(st + 3*T_BYTES  + so, g_pvl + g);
        }
        cpa_commit();
    };
    load_kv(0, 0);

    // ldmatrix lane offsets (144B row stride)
    const uint32_t qoff = (uint32_t)(w * 16 + (lane & 15)) * 144 + ((lane >> 4) << 4);
    const uint32_t koff = (uint32_t)(((lane >> 4) << 3) + (lane & 7)) * 144
                        + (((lane >> 3) & 1) << 4);
    const uint32_t voff = (uint32_t)((((lane >> 3) & 1) << 3) + (lane & 7)) * 144
                        + ((lane >> 4) << 4);

    float m[2] = {-1e30f, -1e30f}, l[2] = {0.f, 0.f};
    float acc[8][4];
#pragma unroll
    for (int nj = 0; nj < 8; nj++)
#pragma unroll
        for (int e = 0; e < 4; e++) acc[nj][e] = 0.f;

    for (int t = 0; t <= qt; t++) {
        const int s = t & 1;
        if (t < qt) {
            load_kv(t + 1, s ^ 1);
            asm volatile("cp.async.wait_group 1;" ::: "memory");
        } else {
            asm volatile("cp.async.wait_group 0;" ::: "memory");
        }
        __syncthreads();
        const uint32_t st = sb + 2 * T_BYTES + s * ST_SZ;

        // ---- QK^T: sf[nj] covers keys nj*8..+7 for this warp's 16 rows ----
        float sf[8][4];
#pragma unroll
        for (int nj = 0; nj < 8; nj++)
#pragma unroll
            for (int e = 0; e < 4; e++) sf[nj][e] = 0.f;
#pragma unroll
        for (int kc = 0; kc < 4; kc++) {
            uint32_t aH[4], aL[4];
            ldsm4(aH, sb           + qoff + kc * 32);
            ldsm4(aL, sb + T_BYTES + qoff + kc * 32);
#pragma unroll
            for (int g = 0; g < 4; g++) {
                uint32_t bh[4], bl[4];
                ldsm4(bh, st           + koff + (uint32_t)g * (16*144) + kc * 32);
                ldsm4(bl, st + T_BYTES + koff + (uint32_t)g * (16*144) + kc * 32);
                mma16816(sf[2*g],   aH, bh[0], bh[1]);
                mma16816(sf[2*g],   aH, bl[0], bl[1]);
                mma16816(sf[2*g],   aL, bh[0], bh[1]);
                mma16816(sf[2*g+1], aH, bh[2], bh[3]);
                mma16816(sf[2*g+1], aH, bl[2], bl[3]);
                mma16816(sf[2*g+1], aL, bh[2], bh[3]);
            }
        }

        // ---- causal mask (diagonal tile only; indices tile-local) ----
        if (t == qt) {
            const int row0 = w * 16 + (lane >> 2);
#pragma unroll
            for (int nj = 0; nj < 8; nj++) {
                const int kb = nj * 8 + (lane & 3) * 2;
                if (kb     > row0)     sf[nj][0] = -1e30f;
                if (kb + 1 > row0)     sf[nj][1] = -1e30f;
                if (kb     > row0 + 8) sf[nj][2] = -1e30f;
                if (kb + 1 > row0 + 8) sf[nj][3] = -1e30f;
            }
        }

        // ---- online softmax on fragments ----
#pragma unroll
        for (int r = 0; r < 2; r++) {
            float mx = -1e30f;
#pragma unroll
            for (int nj = 0; nj < 8; nj++)
                mx = fmaxf(mx, fmaxf(sf[nj][2*r], sf[nj][2*r+1]));
            mx = fmaxf(mx, __shfl_xor_sync(0xffffffffu, mx, 1));
            mx = fmaxf(mx, __shfl_xor_sync(0xffffffffu, mx, 2));
            const float mn = fmaxf(m[r], mx);
            const float corr = __expf(m[r] - mn);
            m[r] = mn;
            float rs = 0.f;
#pragma unroll
            for (int nj = 0; nj < 8; nj++) {
                sf[nj][2*r]   = __expf(sf[nj][2*r]   - mn);
                sf[nj][2*r+1] = __expf(sf[nj][2*r+1] - mn);
                rs += sf[nj][2*r] + sf[nj][2*r+1];
            }
            rs += __shfl_xor_sync(0xffffffffu, rs, 1);
            rs += __shfl_xor_sync(0xffffffffu, rs, 2);
            l[r] = l[r] * corr + rs;
#pragma unroll
            for (int nj = 0; nj < 8; nj++) {
                acc[nj][2*r]   *= corr;
                acc[nj][2*r+1] *= corr;
            }
        }

        // ---- PV: P (regs, hi/lo) x V (ldmatrix.trans, hi/lo) ----
#pragma unroll
        for (int kc = 0; kc < 4; kc++) {
            uint32_t ph[4], pl[4];
#pragma unroll
            for (int e = 0; e < 4; e++) {
                const int jj = 2*kc + (e >> 1);
                split2(sf[jj][(e & 1) * 2], sf[jj][(e & 1) * 2 + 1], ph[e], pl[e]);
            }
#pragma unroll
            for (int ng = 0; ng < 4; ng++) {
                uint32_t vh[4], vl[4];
                const uint32_t va = voff + (uint32_t)kc * (16*144) + (uint32_t)ng * 32;
                ldsm4t(vh, st + 2*T_BYTES + va);
                ldsm4t(vl, st + 3*T_BYTES + va);
                mma16816(acc[2*ng],   ph, vh[0], vh[1]);
                mma16816(acc[2*ng],   ph, vl[0], vl[1]);
                mma16816(acc[2*ng],   pl, vh[0], vh[1]);
                mma16816(acc[2*ng+1], ph, vh[2], vh[3]);
                mma16816(acc[2*ng+1], ph, vl[2], vl[3]);
                mma16816(acc[2*ng+1], pl, vh[2], vh[3]);
            }
        }
        __syncthreads();     // compute done before next iter refills this stage
    }

    // ---- epilogue: normalize, hi/lo split, store ----
    const float inv0 = 1.f / l[0], inv1 = 1.f / l[1];
    const size_t base0 = rowbase + (size_t)(q0 + w * 16 + (lane >> 2)) * HD;
    const size_t base1 = base0 + 8 * HD;
#pragma unroll
    for (int nj = 0; nj < 8; nj++) {
        const int col = nj * 8 + (lane & 3) * 2;
        uint32_t hh, ll;
        split2(acc[nj][0] * inv0, acc[nj][1] * inv0, hh, ll);
        *(uint32_t*)(g_poh + base0 + col) = hh;
        *(uint32_t*)(g_pol + base0 + col) = ll;
        split2(acc[nj][2] * inv1, acc[nj][3] * inv1, hh, ll);
        *(uint32_t*)(g_poh + base1 + col) = hh;
        *(uint32_t*)(g_pol + base1 + col) = ll;
    }
}

// ---------------------------------------------------------------------------
// Inputs: queries, keys, values, mask(ignored), W_Q, W_K, W_V, W_O
// ---------------------------------------------------------------------------
extern "C" void kernel_launch(void* const* d_in, const int* in_sizes, int n_in,
                              void* d_out, int out_size)
{
    (void)in_sizes; (void)n_in; (void)out_size;
    const float* q  = (const float*)d_in[0];
    const float* k  = (const float*)d_in[1];
    const float* v  = (const float*)d_in[2];
    const float* wq = (const float*)d_in[4];
    const float* wk = (const float*)d_in[5];
    const float* wv = (const float*)d_in[6];
    const float* wo = (const float*)d_in[7];
    float* out = (float*)d_out;

    cudaFuncSetAttribute(mmagemm,
                         cudaFuncAttributeMaxDynamicSharedMemorySize, G_SMEM);
    cudaFuncSetAttribute(attn_mma,
                         cudaFuncAttributeMaxDynamicSharedMemorySize, ATT_SMEM);

    const int nCvt = (MM * DD / 4) / 256;     // 8192 blocks

    cvt_hl<<<nCvt, 256>>>(q, 0);
    cvt_hl<<<nCvt, 256>>>(k, 1);
    cvt_hl<<<nCvt, 256>>>(v, 2);
    cvtT<<<dim3(32, 32), 256>>>(wq, 0);
    cvtT<<<dim3(32, 32), 256>>>(wk, 1);
    cvtT<<<dim3(32, 32), 256>>>(wv, 2);
    cvtT<<<dim3(32, 32), 256>>>(wo, 3);

    dim3 gg(HD / 128, MM / 128);              // (8, 64)
    mmagemm<<<gg, 256, G_SMEM>>>(nullptr, 0);
    mmagemm<<<gg, 256, G_SMEM>>>(nullptr, 1);
    mmagemm<<<gg, 256, G_SMEM>>>(nullptr, 2);

    attn_mma<<<dim3(SS / 64, BB * HH), 128, ATT_SMEM>>>();

    mmagemm<<<gg, 256, G_SMEM>>>(out, 3);
}

// round 5
// speedup vs baseline: 3.1405x; 1.1182x over previous
#include <cuda_runtime.h>
#include <cuda_bf16.h>
#include <math.h>
#include <cstdint>

// Problem constants
#define BB 4
#define SS 2048
#define DD 1024
#define HH 16
#define MM (BB*SS)          // 8192
#define HD 1024             // H*DK

typedef __nv_bfloat16 bf16;

// ---------------- scratch (__device__ globals; no allocs allowed) ----------
__device__ bf16 g_qh[MM*DD], g_ql[MM*DD];          // input splits
__device__ bf16 g_kh[MM*DD], g_kl[MM*DD];
__device__ bf16 g_vh[MM*DD], g_vl[MM*DD];
__device__ bf16 g_wh[4][DD*HD], g_wl[4][DD*HD];    // weights^T [N][K] hi/lo
__device__ bf16 g_pqh[MM*HD], g_pql[MM*HD];        // projected Q (pre-scaled)
__device__ bf16 g_pkh[MM*HD], g_pkl[MM*HD];        // projected K
__device__ bf16 g_pvh[MM*HD], g_pvl[MM*HD];        // projected V
__device__ bf16 g_poh[MM*HD], g_pol[MM*HD];        // attention output

// ---------------- PTX helpers ----------------------------------------------
__device__ __forceinline__ uint32_t smem_u32(const void* p) {
    uint32_t a;
    asm("{ .reg .u64 t; cvta.to.shared.u64 t, %1; cvt.u32.u64 %0, t; }"
        : "=r"(a) : "l"(p));
    return a;
}
__device__ __forceinline__ void cpa16(uint32_t s, const void* g) {
    asm volatile("cp.async.cg.shared.global [%0], [%1], 16;" :: "r"(s), "l"(g));
}
__device__ __forceinline__ void cpa_commit() {
    asm volatile("cp.async.commit_group;" ::: "memory");
}
__device__ __forceinline__ void ldsm4(uint32_t* r, uint32_t a) {
    asm volatile("ldmatrix.sync.aligned.m8n8.x4.shared.b16 {%0,%1,%2,%3}, [%4];"
                 : "=r"(r[0]), "=r"(r[1]), "=r"(r[2]), "=r"(r[3]) : "r"(a));
}
__device__ __forceinline__ void ldsm4t(uint32_t* r, uint32_t a) {
    asm volatile("ldmatrix.sync.aligned.m8n8.x4.trans.shared.b16 {%0,%1,%2,%3}, [%4];"
                 : "=r"(r[0]), "=r"(r[1]), "=r"(r[2]), "=r"(r[3]) : "r"(a));
}
__device__ __forceinline__ void mma16816(float* c, const uint32_t* a,
                                         uint32_t b0, uint32_t b1) {
    asm volatile(
        "mma.sync.aligned.m16n8k16.row.col.f32.bf16.bf16.f32 "
        "{%0,%1,%2,%3}, {%4,%5,%6,%7}, {%8,%9}, {%0,%1,%2,%3};"
        : "+f"(c[0]), "+f"(c[1]), "+f"(c[2]), "+f"(c[3])
        : "r"(a[0]), "r"(a[1]), "r"(a[2]), "r"(a[3]), "r"(b0), "r"(b1));
}
// pack2(v0,v1): low half = bf16(v0), high half = bf16(v1)
__device__ __forceinline__ uint32_t pk2(float v0, float v1) {
    uint32_t d;
    asm("cvt.rn.bf16x2.f32 %0, %1, %2;" : "=r"(d) : "f"(v1), "f"(v0));
    return d;
}
__device__ __forceinline__ void split2(float v0, float v1, uint32_t& hi, uint32_t& lo) {
    hi = pk2(v0, v1);
    float h0 = __uint_as_float(hi << 16);
    float h1 = __uint_as_float(hi & 0xffff0000u);
    lo = pk2(v0 - h0, v1 - h1);
}

// ---------------------------------------------------------------------------
// fp32 -> bf16 hi/lo split of q/k/v inputs. blockIdx.y selects tensor.
// ---------------------------------------------------------------------------
__global__ __launch_bounds__(256) void cvt_hl(const float* __restrict__ q,
                                              const float* __restrict__ k,
                                              const float* __restrict__ v)
{
    const int dsel = blockIdx.y;
    const float* src; bf16 *h, *l;
    if      (dsel == 0) { src = q; h = g_qh; l = g_ql; }
    else if (dsel == 1) { src = k; h = g_kh; l = g_kl; }
    else                { src = v; h = g_vh; l = g_vl; }
    int i = blockIdx.x * 256 + threadIdx.x;       // indexes float4
    float4 vv = ((const float4*)src)[i];
    uint32_t h01, l01, h23, l23;
    split2(vv.x, vv.y, h01, l01);
    split2(vv.z, vv.w, h23, l23);
    ((uint32_t*)h)[i*2]   = h01; ((uint32_t*)h)[i*2+1] = h23;
    ((uint32_t*)l)[i*2]   = l01; ((uint32_t*)l)[i*2+1] = l23;
}

// ---------------------------------------------------------------------------
// Weight transpose + hi/lo split. blockIdx.z selects which weight.
// ---------------------------------------------------------------------------
__global__ __launch_bounds__(256) void cvtT(const float* __restrict__ wq,
                                            const float* __restrict__ wk,
                                            const float* __restrict__ wv,
                                            const float* __restrict__ wo)
{
    const int dsel = blockIdx.z;
    const float* W = (dsel == 0) ? wq : (dsel == 1) ? wk : (dsel == 2) ? wv : wo;
    bf16* Th = g_wh[dsel];
    bf16* Tl = g_wl[dsel];
    __shared__ float t[32][33];
    int bx = blockIdx.x * 32;   // n
    int by = blockIdx.y * 32;   // k
    int tx = threadIdx.x & 31, ty = threadIdx.x >> 5;
    for (int i = ty; i < 32; i += 8)
        t[i][tx] = W[(size_t)(by + i) * 1024 + bx + tx];
    __syncthreads();
    for (int i = ty; i < 32; i += 8) {
        float x = t[tx][i];
        bf16 hh = __float2bfloat16_rn(x);
        bf16 ll = __float2bfloat16_rn(x - __bfloat162float(hh));
        Th[(size_t)(bx + i) * 1024 + by + tx] = hh;
        Tl[(size_t)(bx + i) * 1024 + by + tx] = ll;
    }
}

// ---------------------------------------------------------------------------
// HMMA GEMM, hi/lo 3-product, CTA 128x128, BK=32, 8 warps, cp.async 2-stage.
// __launch_bounds__(256,2): 2 CTAs/SM (regs<=128; B frags rescoped per pair).
// whichArg < 0: which = blockIdx.z (QKV fused). which 0..2 -> bf16 hi/lo out,
// which 3 -> fp32 out.
// ---------------------------------------------------------------------------
#define TEN_B 10240                 // 128 rows * 80B
#define STG_B (4*TEN_B)
#define G_SMEM (2*STG_B)            // 81920

__global__ __launch_bounds__(256, 2) void mmagemm(float* __restrict__ Cout, int whichArg)
{
    extern __shared__ char smem[];
    const int which = (whichArg < 0) ? (int)blockIdx.z : whichArg;
    const bf16 *Ah, *Al, *Bhp, *Blp;
    bf16 *Chi = nullptr, *Clo = nullptr;
    float scale = 1.f;
    if      (which == 0) { Ah=g_qh;  Al=g_ql;  Bhp=g_wh[0]; Blp=g_wl[0]; Chi=g_pqh; Clo=g_pql; scale=0.125f; }
    else if (which == 1) { Ah=g_kh;  Al=g_kl;  Bhp=g_wh[1]; Blp=g_wl[1]; Chi=g_pkh; Clo=g_pkl; }
    else if (which == 2) { Ah=g_vh;  Al=g_vl;  Bhp=g_wh[2]; Blp=g_wl[2]; Chi=g_pvh; Clo=g_pvl; }
    else                 { Ah=g_poh; Al=g_pol; Bhp=g_wh[3]; Blp=g_wl[3]; }

    const uint32_t sb = smem_u32(smem);
    const int tid = threadIdx.x, wid = tid >> 5, lane = tid & 31;
    const int wm = wid & 3, wn = wid >> 2;
    const int m0 = blockIdx.y * 128, n0 = blockIdx.x * 128;

    float acc[2][8][4];
#pragma unroll
    for (int i = 0; i < 2; i++)
#pragma unroll
        for (int j = 0; j < 8; j++)
#pragma unroll
            for (int q = 0; q < 4; q++) acc[i][j][q] = 0.f;

    const int r0 = tid >> 2, ch0 = tid & 3;
    const int r1 = (tid + 256) >> 2, ch1 = tid & 3;

    auto load_stage = [&](int it, int s) {
        const int kk = it << 5;
        const uint32_t st = sb + s * STG_B;
        const size_t ga0 = (size_t)(m0 + r0) * 1024 + kk + ch0 * 8;
        const size_t ga1 = (size_t)(m0 + r1) * 1024 + kk + ch1 * 8;
        const size_t gb0 = (size_t)(n0 + r0) * 1024 + kk + ch0 * 8;
        const size_t gb1 = (size_t)(n0 + r1) * 1024 + kk + ch1 * 8;
        const uint32_t so0 = r0 * 80 + ch0 * 16;
        const uint32_t so1 = r1 * 80 + ch1 * 16;
        cpa16(st            + so0, Ah  + ga0);
        cpa16(st            + so1, Ah  + ga1);
        cpa16(st +   TEN_B  + so0, Al  + ga0);
        cpa16(st +   TEN_B  + so1, Al  + ga1);
        cpa16(st + 2*TEN_B  + so0, Bhp + gb0);
        cpa16(st + 2*TEN_B  + so1, Bhp + gb1);
        cpa16(st + 3*TEN_B  + so0, Blp + gb0);
        cpa16(st + 3*TEN_B  + so1, Blp + gb1);
        cpa_commit();
    };

    const uint32_t aoff = (uint32_t)(wm * 32 + (lane & 15)) * 80 + ((lane >> 4) << 3) * 2;
    const uint32_t boff = (uint32_t)(wn * 64 + ((lane >> 4) << 3) + (lane & 7)) * 80
                        + (((lane >> 3) & 1) << 3) * 2;

    load_stage(0, 0);
    const int NIT = 32;
    for (int it = 0; it < NIT; it++) {
        const int s = it & 1;
        if (it + 1 < NIT) {
            load_stage(it + 1, s ^ 1);
            asm volatile("cp.async.wait_group 1;" ::: "memory");
        } else {
            asm volatile("cp.async.wait_group 0;" ::: "memory");
        }
        __syncthreads();

        const uint32_t st = sb + s * STG_B;
#pragma unroll
        for (int k16 = 0; k16 < 2; k16++) {
            const uint32_t kb = (uint32_t)(k16 * 16 * 2);
            uint32_t aH[2][4], aL[2][4];
            ldsm4(aH[0], st            + aoff + kb);
            ldsm4(aH[1], st            + aoff + kb + 16 * 80);
            ldsm4(aL[0], st +   TEN_B  + aoff + kb);
            ldsm4(aL[1], st +   TEN_B  + aoff + kb + 16 * 80);
#pragma unroll
            for (int p = 0; p < 4; p++) {          // one B pair live at a time
                uint32_t bh[4], bl[4];
                ldsm4(bh, st + 2*TEN_B + boff + kb + (uint32_t)p * 16 * 80);
                ldsm4(bl, st + 3*TEN_B + boff + kb + (uint32_t)p * 16 * 80);
#pragma unroll
                for (int mi = 0; mi < 2; mi++) {
                    mma16816(acc[mi][2*p],   aH[mi], bh[0], bh[1]);
                    mma16816(acc[mi][2*p],   aH[mi], bl[0], bl[1]);
                    mma16816(acc[mi][2*p],   aL[mi], bh[0], bh[1]);
                    mma16816(acc[mi][2*p+1], aH[mi], bh[2], bh[3]);
                    mma16816(acc[mi][2*p+1], aH[mi], bl[2], bl[3]);
                    mma16816(acc[mi][2*p+1], aL[mi], bh[2], bh[3]);
                }
            }
        }
        __syncthreads();
    }

    // epilogue
#pragma unroll
    for (int mi = 0; mi < 2; mi++)
#pragma unroll
        for (int nj = 0; nj < 8; nj++) {
            const int row = m0 + wm * 32 + mi * 16 + (lane >> 2);
            const int col = n0 + wn * 64 + nj * 8 + (lane & 3) * 2;
            if (which == 3) {
                *(float2*)(Cout + (size_t)row * 1024 + col)
                    = make_float2(acc[mi][nj][0], acc[mi][nj][1]);
                *(float2*)(Cout + (size_t)(row + 8) * 1024 + col)
                    = make_float2(acc[mi][nj][2], acc[mi][nj][3]);
            } else {
                uint32_t hh, ll;
                split2(acc[mi][nj][0]*scale, acc[mi][nj][1]*scale, hh, ll);
                *(uint32_t*)(Chi + (size_t)row * 1024 + col) = hh;
                *(uint32_t*)(Clo + (size_t)row * 1024 + col) = ll;
                split2(acc[mi][nj][2]*scale, acc[mi][nj][3]*scale, hh, ll);
                *(uint32_t*)(Chi + (size_t)(row + 8) * 1024 + col) = hh;
                *(uint32_t*)(Clo + (size_t)(row + 8) * 1024 + col) = ll;
            }
        }
}

// ---------------------------------------------------------------------------
// HMMA causal flash attention. 128 threads (4 warps), q-tile 64, key-tile 64.
// Q fragments hoisted to registers (loaded once). K/V cp.async double-buffered.
// ---------------------------------------------------------------------------
#define T_BYTES (64*144)            // 9216 per tensor tile
#define ST_SZ   (4*T_BYTES)         // Kh,Kl,Vh,Vl
#define ATT_SMEM (2*T_BYTES + 2*ST_SZ)   // 92160

__global__ __launch_bounds__(128) void attn_mma()
{
    extern __shared__ char sm8[];
    const uint32_t sb = smem_u32(sm8);
    const int tid = threadIdx.x, w = tid >> 5, lane = tid & 31;
    const int bh = blockIdx.y, b = bh >> 4, h = bh & 15;
    const int qt = (int)gridDim.x - 1 - blockIdx.x;     // long tiles first
    const int q0 = qt << 6;
    const size_t rowbase = (size_t)b * SS * HD + h * 64;

    // ---- load Q tile (hi+lo), group 0 ----
#pragma unroll
    for (int i = 0; i < 4; i++) {
        int op = tid + (i << 7);
        int r = op >> 3, ch = op & 7;
        size_t g = rowbase + (size_t)(q0 + r) * HD + ch * 8;
        uint32_t so = (uint32_t)r * 144 + ch * 16;
        cpa16(sb + so,           g_pqh + g);
        cpa16(sb + T_BYTES + so, g_pql + g);
    }
    cpa_commit();

    auto load_kv = [&](int t, int s) {
        const int j0 = t << 6;
        const uint32_t st = sb + 2 * T_BYTES + s * ST_SZ;
#pragma unroll
        for (int i = 0; i < 4; i++) {
            int op = tid + (i << 7);
            int r = op >> 3, ch = op & 7;
            size_t g = rowbase + (size_t)(j0 + r) * HD + ch * 8;
            uint32_t so = (uint32_t)r * 144 + ch * 16;
            cpa16(st              + so, g_pkh + g);
            cpa16(st +   T_BYTES  + so, g_pkl + g);
            cpa16(st + 2*T_BYTES  + so, g_pvh + g);
            cpa16(st + 3*T_BYTES  + so, g_pvl + g);
        }
        cpa_commit();
    };
    load_kv(0, 0);

    const uint32_t qoff = (uint32_t)(w * 16 + (lane & 15)) * 144 + ((lane >> 4) << 4);
    const uint32_t koff = (uint32_t)(((lane >> 4) << 3) + (lane & 7)) * 144
                        + (((lane >> 3) & 1) << 4);
    const uint32_t voff = (uint32_t)((((lane >> 3) & 1) << 3) + (lane & 7)) * 144
                        + ((lane >> 4) << 4);

    // ---- hoist Q fragments to registers (Q smem stable afterwards) ----
    asm volatile("cp.async.wait_group 1;" ::: "memory");   // Q group complete
    __syncthreads();
    uint32_t qH[4][4], qL[4][4];
#pragma unroll
    for (int kc = 0; kc < 4; kc++) {
        ldsm4(qH[kc], sb           + qoff + kc * 32);
        ldsm4(qL[kc], sb + T_BYTES + qoff + kc * 32);
    }

    float m[2] = {-1e30f, -1e30f}, l[2] = {0.f, 0.f};
    float acc[8][4];
#pragma unroll
    for (int nj = 0; nj < 8; nj++)
#pragma unroll
        for (int e = 0; e < 4; e++) acc[nj][e] = 0.f;

    for (int t = 0; t <= qt; t++) {
        const int s = t & 1;
        if (t < qt) {
            load_kv(t + 1, s ^ 1);
            asm volatile("cp.async.wait_group 1;" ::: "memory");
        } else {
            asm volatile("cp.async.wait_group 0;" ::: "memory");
        }
        __syncthreads();
        const uint32_t st = sb + 2 * T_BYTES + s * ST_SZ;

        // ---- QK^T ----
        float sf[8][4];
#pragma unroll
        for (int nj = 0; nj < 8; nj++)
#pragma unroll
            for (int e = 0; e < 4; e++) sf[nj][e] = 0.f;
#pragma unroll
        for (int kc = 0; kc < 4; kc++) {
#pragma unroll
            for (int g = 0; g < 4; g++) {
                uint32_t bh[4], bl[4];
                ldsm4(bh, st           + koff + (uint32_t)g * (16*144) + kc * 32);
                ldsm4(bl, st + T_BYTES + koff + (uint32_t)g * (16*144) + kc * 32);
                mma16816(sf[2*g],   qH[kc], bh[0], bh[1]);
                mma16816(sf[2*g],   qH[kc], bl[0], bl[1]);
                mma16816(sf[2*g],   qL[kc], bh[0], bh[1]);
                mma16816(sf[2*g+1], qH[kc], bh[2], bh[3]);
                mma16816(sf[2*g+1], qH[kc], bl[2], bl[3]);
                mma16816(sf[2*g+1], qL[kc], bh[2], bh[3]);
            }
        }

        // ---- causal mask (diagonal tile only; tile-local indices) ----
        if (t == qt) {
            const int row0 = w * 16 + (lane >> 2);
#pragma unroll
            for (int nj = 0; nj < 8; nj++) {
                const int kb = nj * 8 + (lane & 3) * 2;
                if (kb     > row0)     sf[nj][0] = -1e30f;
                if (kb + 1 > row0)     sf[nj][1] = -1e30f;
                if (kb     > row0 + 8) sf[nj][2] = -1e30f;
                if (kb + 1 > row0 + 8) sf[nj][3] = -1e30f;
            }
        }

        // ---- online softmax on fragments ----
#pragma unroll
        for (int r = 0; r < 2; r++) {
            float mx = -1e30f;
#pragma unroll
            for (int nj = 0; nj < 8; nj++)
                mx = fmaxf(mx, fmaxf(sf[nj][2*r], sf[nj][2*r+1]));
            mx = fmaxf(mx, __shfl_xor_sync(0xffffffffu, mx, 1));
            mx = fmaxf(mx, __shfl_xor_sync(0xffffffffu, mx, 2));
            const float mn = fmaxf(m[r], mx);
            const float corr = __expf(m[r] - mn);
            m[r] = mn;
            float rs = 0.f;
#pragma unroll
            for (int nj = 0; nj < 8; nj++) {
                sf[nj][2*r]   = __expf(sf[nj][2*r]   - mn);
                sf[nj][2*r+1] = __expf(sf[nj][2*r+1] - mn);
                rs += sf[nj][2*r] + sf[nj][2*r+1];
            }
            rs += __shfl_xor_sync(0xffffffffu, rs, 1);
            rs += __shfl_xor_sync(0xffffffffu, rs, 2);
            l[r] = l[r] * corr + rs;
#pragma unroll
            for (int nj = 0; nj < 8; nj++) {
                acc[nj][2*r]   *= corr;
                acc[nj][2*r+1] *= corr;
            }
        }

        // ---- PV ----
#pragma unroll
        for (int kc = 0; kc < 4; kc++) {
            uint32_t ph[4], pl[4];
#pragma unroll
            for (int e = 0; e < 4; e++) {
                const int jj = 2*kc + (e >> 1);
                split2(sf[jj][(e & 1) * 2], sf[jj][(e & 1) * 2 + 1], ph[e], pl[e]);
            }
#pragma unroll
            for (int ng = 0; ng < 4; ng++) {
                uint32_t vh[4], vl[4];
                const uint32_t va = voff + (uint32_t)kc * (16*144) + (uint32_t)ng * 32;
                ldsm4t(vh, st + 2*T_BYTES + va);
                ldsm4t(vl, st + 3*T_BYTES + va);
                mma16816(acc[2*ng],   ph, vh[0], vh[1]);
                mma16816(acc[2*ng],   ph, vl[0], vl[1]);
                mma16816(acc[2*ng],   pl, vh[0], vh[1]);
                mma16816(acc[2*ng+1], ph, vh[2], vh[3]);
                mma16816(acc[2*ng+1], ph, vl[2], vl[3]);
                mma16816(acc[2*ng+1], pl, vh[2], vh[3]);
            }
        }
        __syncthreads();     // compute done before next iter refills this stage
    }

    // ---- epilogue: normalize, hi/lo split, store ----
    const float inv0 = 1.f / l[0], inv1 = 1.f / l[1];
    const size_t base0 = rowbase + (size_t)(q0 + w * 16 + (lane >> 2)) * HD;
    const size_t base1 = base0 + 8 * HD;
#pragma unroll
    for (int nj = 0; nj < 8; nj++) {
        const int col = nj * 8 + (lane & 3) * 2;
        uint32_t hh, ll;
        split2(acc[nj][0] * inv0, acc[nj][1] * inv0, hh, ll);
        *(uint32_t*)(g_poh + base0 + col) = hh;
        *(uint32_t*)(g_pol + base0 + col) = ll;
        split2(acc[nj][2] * inv1, acc[nj][3] * inv1, hh, ll);
        *(uint32_t*)(g_poh + base1 + col) = hh;
        *(uint32_t*)(g_pol + base1 + col) = ll;
    }
}

// ---------------------------------------------------------------------------
// Inputs: queries, keys, values, mask(ignored), W_Q, W_K, W_V, W_O
// ---------------------------------------------------------------------------
extern "C" void kernel_launch(void* const* d_in, const int* in_sizes, int n_in,
                              void* d_out, int out_size)
{
    (void)in_sizes; (void)n_in; (void)out_size;
    const float* q  = (const float*)d_in[0];
    const float* k  = (const float*)d_in[1];
    const float* v  = (const float*)d_in[2];
    const float* wq = (const float*)d_in[4];
    const float* wk = (const float*)d_in[5];
    const float* wv = (const float*)d_in[6];
    const float* wo = (const float*)d_in[7];
    float* out = (float*)d_out;

    cudaFuncSetAttribute(mmagemm,
                         cudaFuncAttributeMaxDynamicSharedMemorySize, G_SMEM);
    cudaFuncSetAttribute(attn_mma,
                         cudaFuncAttributeMaxDynamicSharedMemorySize, ATT_SMEM);

    const int nCvt = (MM * DD / 4) / 256;     // 8192 blocks

    cvt_hl<<<dim3(nCvt, 3), 256>>>(q, k, v);
    cvtT<<<dim3(32, 32, 4), 256>>>(wq, wk, wv, wo);

    // fused QKV projections (blockIdx.z selects)
    mmagemm<<<dim3(HD / 128, MM / 128, 3), 256, G_SMEM>>>(nullptr, -1);

    attn_mma<<<dim3(SS / 64, BB * HH), 128, ATT_SMEM>>>();

    mmagemm<<<dim3(HD / 128, MM / 128, 1), 256, G_SMEM>>>(out, 3);
}